// round 2
// baseline (speedup 1.0000x reference)
#include <cuda_runtime.h>
#include <cstddef>

// Problem constants (fixed by setup_inputs)
#define T_LEN 2048
#define B_SZ  16
#define H_SZ  1024
#define N3    (3 * H_SZ)
#define M_ROWS (T_LEN * B_SZ)

// Scratch (device globals: allocation-free rule). Padded by one t-row so the
// scan's next-step prefetch never reads out of bounds.
__device__ float g_U0p[8 * N3];
__device__ float g_U0[N3];
__device__ float g_hA[(size_t)M_ROWS * H_SZ + (size_t)B_SZ * H_SZ];
__device__ float g_hB[(size_t)M_ROWS * H_SZ + (size_t)B_SZ * H_SZ];
__device__ float g_U [(size_t)M_ROWS * N3  + (size_t)B_SZ * N3];

__device__ __forceinline__ float sigmoidf_(float x) {
    return 1.0f / (1.0f + __expf(-x));
}

// ---------------------------------------------------------------------------
// Layer-0 U: U0[n] = sum_k inp[k] * W0[k, n]   (single [3H] vector)
// ---------------------------------------------------------------------------
__global__ void gemv_part_kernel(const float* __restrict__ inp,
                                 const float* __restrict__ W0,
                                 float* __restrict__ U0p) {
    int n  = blockIdx.x * 128 + threadIdx.x;   // 24 * 128 = 3072 columns
    int k0 = blockIdx.y * 128;                 // 8 k-slices of 128
    const float* wp = W0 + (size_t)k0 * N3 + n;
    float s = 0.f;
#pragma unroll 8
    for (int k = 0; k < 128; k++) {
        s = fmaf(inp[k0 + k], *wp, s);
        wp += N3;
    }
    U0p[blockIdx.y * N3 + n] = s;
}

__global__ void gemv_red_kernel(const float* __restrict__ U0p,
                                float* __restrict__ U0) {
    int n = blockIdx.x * 256 + threadIdx.x;
    if (n < N3) {
        float s = 0.f;
#pragma unroll
        for (int i = 0; i < 8; i++) s += U0p[i * N3 + n];
        U0[n] = s;
    }
}

// ---------------------------------------------------------------------------
// Layer-0 scan: U constant over t, x constant over (t,b). Pure register loop.
// ---------------------------------------------------------------------------
__global__ void scan0_kernel(const float* __restrict__ U0,
                             const float* __restrict__ inp,
                             const float* __restrict__ c0,
                             const float* __restrict__ Vl,
                             const float* __restrict__ bl,
                             float* __restrict__ hout) {
    int j = blockIdx.x * blockDim.x + threadIdx.x;   // 0 .. B*H-1
    int h = j & (H_SZ - 1);
    float u0 = U0[h], u1 = U0[H_SZ + h], u2 = U0[2 * H_SZ + h];
    float xv = inp[h];
    float c  = c0[j];
    float vf = Vl[h], vr = Vl[H_SZ + h];
    float bf = bl[h], br = bl[H_SZ + h];
    float* out = hout + j;
#pragma unroll 4
    for (int t = 0; t < T_LEN; t++) {
        float f = sigmoidf_(fmaf(vf, c, u1) + bf);
        c = fmaf(f, c - u0, u0);                 // f*c + (1-f)*u0
        float r = sigmoidf_(fmaf(vr, c, u2) + br);
        *out = fmaf(r, c - xv, xv);              // r*c + (1-r)*x
        out += B_SZ * H_SZ;
    }
}

// ---------------------------------------------------------------------------
// Generic layer scan (layers 1..3). One thread per (b,h) lane; software
// prefetch of the next timestep's U/x to double memory-level parallelism.
// final_out != 0: write permuted [B, T, H] directly into d_out.
// ---------------------------------------------------------------------------
__global__ void scan_kernel(const float* __restrict__ U,
                            const float* __restrict__ xin,
                            const float* __restrict__ c0,
                            const float* __restrict__ Vl,
                            const float* __restrict__ bl,
                            float* __restrict__ hout,
                            int final_out) {
    int j = blockIdx.x * blockDim.x + threadIdx.x;   // 0 .. B*H-1
    int b = j >> 10;
    int h = j & (H_SZ - 1);
    float c  = c0[j];
    float vf = Vl[h], vr = Vl[H_SZ + h];
    float bf = bl[h], br = bl[H_SZ + h];

    const float* pu = U + (size_t)b * N3 + h;        // row m = t*B + b
    const float* px = xin + j;
    const size_t su = (size_t)B_SZ * N3;
    const size_t sx = (size_t)B_SZ * H_SZ;

    float u0 = pu[0], u1 = pu[H_SZ], u2 = pu[2 * H_SZ], xv = px[0];

    float* out;
    size_t ostride;
    if (final_out) { out = hout + (size_t)b * T_LEN * H_SZ + h; ostride = H_SZ; }
    else           { out = hout + j;                            ostride = (size_t)B_SZ * H_SZ; }

    for (int t = 0; t < T_LEN; t++) {
        pu += su; px += sx;                          // prefetch t+1 (padded)
        float nu0 = pu[0], nu1 = pu[H_SZ], nu2 = pu[2 * H_SZ], nxv = px[0];

        float f = sigmoidf_(fmaf(vf, c, u1) + bf);
        c = fmaf(f, c - u0, u0);
        float r = sigmoidf_(fmaf(vr, c, u2) + br);
        *out = fmaf(r, c - xv, xv);
        out += ostride;

        u0 = nu0; u1 = nu1; u2 = nu2; xv = nxv;
    }
}

// ---------------------------------------------------------------------------
// fp32 SGEMM: C[M_ROWS, N3] = A[M_ROWS, H_SZ] @ B[H_SZ, N3]
// 128x128 block tile, BK=8, 256 threads, 8x8 per thread in a 4+4 split layout
// (conflict-free LDS.128 fragment loads).
// ---------------------------------------------------------------------------
__global__ void __launch_bounds__(256, 2)
sgemm_kernel(const float* __restrict__ A, const float* __restrict__ B,
             float* __restrict__ C) {
    const int K = H_SZ, N = N3;
    __shared__ float As[8][128];
    __shared__ float Bs[8][128];

    int tid = threadIdx.x;
    int tx = tid & 15, ty = tid >> 4;
    int a_row = tid >> 1,  a_col = (tid & 1) << 2;     // 128 rows x 8 k
    int b_row = tid >> 5,  b_col = (tid & 31) << 2;    // 8 rows x 128 n

    const float* Ap = A + (size_t)(blockIdx.y * 128 + a_row) * K + a_col;
    const float* Bp = B + (size_t)b_row * N + blockIdx.x * 128 + b_col;

    float acc[8][8] = {};

    for (int k0 = 0; k0 < K; k0 += 8) {
        float4 av = *reinterpret_cast<const float4*>(Ap);
        float4 bv = *reinterpret_cast<const float4*>(Bp);
        As[a_col + 0][a_row] = av.x;
        As[a_col + 1][a_row] = av.y;
        As[a_col + 2][a_row] = av.z;
        As[a_col + 3][a_row] = av.w;
        *reinterpret_cast<float4*>(&Bs[b_row][b_col]) = bv;
        __syncthreads();

#pragma unroll
        for (int kk = 0; kk < 8; kk++) {
            float4 a0 = *reinterpret_cast<const float4*>(&As[kk][ty * 4]);
            float4 a1 = *reinterpret_cast<const float4*>(&As[kk][64 + ty * 4]);
            float4 b0 = *reinterpret_cast<const float4*>(&Bs[kk][tx * 4]);
            float4 b1 = *reinterpret_cast<const float4*>(&Bs[kk][64 + tx * 4]);
            float ar[8] = {a0.x, a0.y, a0.z, a0.w, a1.x, a1.y, a1.z, a1.w};
            float br[8] = {b0.x, b0.y, b0.z, b0.w, b1.x, b1.y, b1.z, b1.w};
#pragma unroll
            for (int i = 0; i < 8; i++)
#pragma unroll
                for (int jj = 0; jj < 8; jj++)
                    acc[i][jj] = fmaf(ar[i], br[jj], acc[i][jj]);
        }
        __syncthreads();
        Ap += 8;
        Bp += (size_t)8 * N;
    }

#pragma unroll
    for (int i = 0; i < 8; i++) {
        int rloc = (i < 4) ? (ty * 4 + i) : (64 + ty * 4 + (i - 4));
        float* Cp = C + (size_t)(blockIdx.y * 128 + rloc) * N + blockIdx.x * 128;
        *reinterpret_cast<float4*>(Cp + tx * 4) =
            make_float4(acc[i][0], acc[i][1], acc[i][2], acc[i][3]);
        *reinterpret_cast<float4*>(Cp + 64 + tx * 4) =
            make_float4(acc[i][4], acc[i][5], acc[i][6], acc[i][7]);
    }
}

// ---------------------------------------------------------------------------
// Inputs (metadata order): 0:c_n[B,H] 1:max_len(int) 2:inp_vec[H]
//                          3:W[NL,H,3H] 4:V[NL,2H] 5:bias[NL,2H]
// ---------------------------------------------------------------------------
extern "C" void kernel_launch(void* const* d_in, const int* in_sizes, int n_in,
                              void* d_out, int out_size) {
    const float* c_n  = (const float*)d_in[0];
    const float* inp  = (const float*)d_in[2];
    const float* W    = (const float*)d_in[3];
    const float* V    = (const float*)d_in[4];
    const float* bias = (const float*)d_in[5];
    float* out = (float*)d_out;

    float *pU0p, *pU0, *phA, *phB, *pU;
    cudaGetSymbolAddress((void**)&pU0p, g_U0p);
    cudaGetSymbolAddress((void**)&pU0,  g_U0);
    cudaGetSymbolAddress((void**)&phA,  g_hA);
    cudaGetSymbolAddress((void**)&phB,  g_hB);
    cudaGetSymbolAddress((void**)&pU,   g_U);

    // Layer 0: GEMV + register-resident scan
    gemv_part_kernel<<<dim3(24, 8), 128>>>(inp, W, pU0p);
    gemv_red_kernel<<<12, 256>>>(pU0p, pU0);
    scan0_kernel<<<64, 256>>>(pU0, inp, c_n, V, bias, phA);

    // Layers 1..3: GEMM + scan
    const float* cur = phA;
    for (int l = 1; l < 4; l++) {
        sgemm_kernel<<<dim3(24, 256), 256>>>(cur, W + (size_t)l * H_SZ * N3, pU);
        int fin = (l == 3);
        float* nxt = fin ? out : ((cur == phA) ? phB : phA);
        scan_kernel<<<64, 256>>>(pU, cur, c_n,
                                 V + (size_t)l * 2 * H_SZ,
                                 bias + (size_t)l * 2 * H_SZ,
                                 nxt, fin);
        cur = nxt;
    }
}

// round 4
// speedup vs baseline: 1.4359x; 1.4359x over previous
#include <cuda_runtime.h>
#include <cuda_bf16.h>
#include <cstdint>
#include <cstddef>

#define T_LEN 2048
#define B_SZ  16
#define H_SZ  1024
#define N3    (3 * H_SZ)
#define M_ROWS (T_LEN * B_SZ)
#define KDIM  H_SZ

// mma.sync GEMM tiling
#define BM 128
#define BN 128
#define BK 32
#define NSTAGE 4
#define NCHUNK 96                    // 3 split passes * (1024/32)
#define A_ROW_B 80                   // 32 bf16 = 64B data, padded to 80B (5x16B)
#define B_ROW_B 272                  // 128 bf16 = 256B data, padded to 272B (17x16B)
#define AS_BYTES (BM * A_ROW_B)      // 10240
#define BS_BYTES (BK * B_ROW_B)      // 8704
#define SMEM_TOTAL (NSTAGE * (AS_BYTES + BS_BYTES))   // 75776

// ---------------- scratch (device globals; allocation-free rule) -----------
__device__ float g_U0p[8 * N3];
__device__ float g_U0[N3];
__device__ float g_hA[(size_t)M_ROWS * H_SZ + (size_t)B_SZ * H_SZ];
__device__ float g_hB[(size_t)M_ROWS * H_SZ + (size_t)B_SZ * H_SZ];
__device__ float g_U [(size_t)M_ROWS * N3  + (size_t)B_SZ * N3];
__device__ __nv_bfloat16 g_Ahi[(size_t)M_ROWS * KDIM];
__device__ __nv_bfloat16 g_Alo[(size_t)M_ROWS * KDIM];
__device__ __nv_bfloat16 g_Whi[(size_t)3 * KDIM * N3];
__device__ __nv_bfloat16 g_Wlo[(size_t)3 * KDIM * N3];

__device__ __forceinline__ float sigmoidf_(float x) {
    return 1.0f / (1.0f + __expf(-x));
}

__device__ __forceinline__ uint32_t smem_u32(const void* p) {
    uint32_t a;
    asm("{ .reg .u64 t; cvta.to.shared.u64 t, %1; cvt.u32.u64 %0, t; }"
        : "=r"(a) : "l"(p));
    return a;
}
__device__ __forceinline__ void cp16(uint32_t dst, const void* src) {
    asm volatile("cp.async.cg.shared.global [%0], [%1], 16;"
                 :: "r"(dst), "l"(src) : "memory");
}
__device__ __forceinline__ void ldm_x4(uint32_t& r0, uint32_t& r1,
                                       uint32_t& r2, uint32_t& r3, uint32_t a) {
    asm volatile("ldmatrix.sync.aligned.m8n8.x4.shared.b16 {%0,%1,%2,%3}, [%4];"
                 : "=r"(r0), "=r"(r1), "=r"(r2), "=r"(r3) : "r"(a));
}
__device__ __forceinline__ void ldm_x4t(uint32_t& r0, uint32_t& r1,
                                        uint32_t& r2, uint32_t& r3, uint32_t a) {
    asm volatile("ldmatrix.sync.aligned.m8n8.x4.trans.shared.b16 {%0,%1,%2,%3}, [%4];"
                 : "=r"(r0), "=r"(r1), "=r"(r2), "=r"(r3) : "r"(a));
}
__device__ __forceinline__ void mma_bf16(float* c, uint32_t a0, uint32_t a1,
                                         uint32_t a2, uint32_t a3,
                                         uint32_t b0, uint32_t b1) {
    asm volatile(
        "mma.sync.aligned.m16n8k16.row.col.f32.bf16.bf16.f32 "
        "{%0,%1,%2,%3}, {%4,%5,%6,%7}, {%8,%9}, {%0,%1,%2,%3};"
        : "+f"(c[0]), "+f"(c[1]), "+f"(c[2]), "+f"(c[3])
        : "r"(a0), "r"(a1), "r"(a2), "r"(a3), "r"(b0), "r"(b1));
}

// ---------------------------------------------------------------------------
// Split conversions
// ---------------------------------------------------------------------------
__global__ void split_a_kernel(const float* __restrict__ x,
                               __nv_bfloat16* __restrict__ hi,
                               __nv_bfloat16* __restrict__ lo) {
    size_t i = ((size_t)blockIdx.x * 256 + threadIdx.x) * 4;
    float4 v = *reinterpret_cast<const float4*>(x + i);
    __nv_bfloat16 h0 = __float2bfloat16(v.x), h1 = __float2bfloat16(v.y);
    __nv_bfloat16 h2 = __float2bfloat16(v.z), h3 = __float2bfloat16(v.w);
    __nv_bfloat162 hp0(h0, h1), hp1(h2, h3);
    __nv_bfloat162 lp0(__float2bfloat16(v.x - __bfloat162float(h0)),
                       __float2bfloat16(v.y - __bfloat162float(h1)));
    __nv_bfloat162 lp1(__float2bfloat16(v.z - __bfloat162float(h2)),
                       __float2bfloat16(v.w - __bfloat162float(h3)));
    *reinterpret_cast<__nv_bfloat162*>(hi + i)     = hp0;
    *reinterpret_cast<__nv_bfloat162*>(hi + i + 2) = hp1;
    *reinterpret_cast<__nv_bfloat162*>(lo + i)     = lp0;
    *reinterpret_cast<__nv_bfloat162*>(lo + i + 2) = lp1;
}

// Elementwise split of W layers 1..3 ([K,N] layout preserved)
__global__ void split_w_kernel(const float* __restrict__ W,
                               __nv_bfloat16* __restrict__ hi,
                               __nv_bfloat16* __restrict__ lo) {
    size_t i = ((size_t)blockIdx.x * 256 + threadIdx.x) * 4;
    const float* src = W + (size_t)KDIM * N3;    // skip layer 0
    float4 v = *reinterpret_cast<const float4*>(src + i);
    __nv_bfloat16 h0 = __float2bfloat16(v.x), h1 = __float2bfloat16(v.y);
    __nv_bfloat16 h2 = __float2bfloat16(v.z), h3 = __float2bfloat16(v.w);
    __nv_bfloat162 hp0(h0, h1), hp1(h2, h3);
    __nv_bfloat162 lp0(__float2bfloat16(v.x - __bfloat162float(h0)),
                       __float2bfloat16(v.y - __bfloat162float(h1)));
    __nv_bfloat162 lp1(__float2bfloat16(v.z - __bfloat162float(h2)),
                       __float2bfloat16(v.w - __bfloat162float(h3)));
    *reinterpret_cast<__nv_bfloat162*>(hi + i)     = hp0;
    *reinterpret_cast<__nv_bfloat162*>(hi + i + 2) = hp1;
    *reinterpret_cast<__nv_bfloat162*>(lo + i)     = lp0;
    *reinterpret_cast<__nv_bfloat162*>(lo + i + 2) = lp1;
}

// ---------------------------------------------------------------------------
// bf16 mma.sync GEMM with 3-pass split accumulation.
// C[M_ROWS, N3] = Ahi@Whi + Ahi@Wlo + Alo@Whi  (fp32 accum)
// Block 128x128, BK=32, 4-stage cp.async pipeline, 8 warps (warp tile 64x32).
// ---------------------------------------------------------------------------
__global__ void __launch_bounds__(256, 1)
mma_gemm_kernel(const __nv_bfloat16* __restrict__ Ahi,
                const __nv_bfloat16* __restrict__ Alo,
                const __nv_bfloat16* __restrict__ Whi,
                const __nv_bfloat16* __restrict__ Wlo,
                float* __restrict__ C, int layer) {
    extern __shared__ char smem[];
    const uint32_t sb = smem_u32(smem);
    const int tid = threadIdx.x;
    const int wid = tid >> 5, lane = tid & 31;
    const int m0 = blockIdx.y * BM;
    const int n0 = blockIdx.x * BN;
    const int wm = (wid & 1) * 64;          // warp m offset
    const int wn = (wid >> 1) * 32;         // warp n offset

    const __nv_bfloat16* Bhi = Whi + (size_t)layer * KDIM * N3;
    const __nv_bfloat16* Blo = Wlo + (size_t)layer * KDIM * N3;

    // load chunk c (pass p, k-offset) into stage s
    auto load_chunk = [&](int c, int s) {
        int p = c >> 5;
        int koff = (c & 31) * BK;
        const __nv_bfloat16* As = (p == 2) ? Alo : Ahi;
        const __nv_bfloat16* Bs = (p == 1) ? Blo : Bhi;
        uint32_t ab = sb + s * AS_BYTES;
        uint32_t bb = sb + NSTAGE * AS_BYTES + s * BS_BYTES;
#pragma unroll
        for (int g = tid; g < 512; g += 256) {            // A: 128 rows x 4x16B
            int r = g >> 2, ch = g & 3;
            cp16(ab + r * A_ROW_B + ch * 16,
                 As + (size_t)(m0 + r) * KDIM + koff + ch * 8);
        }
#pragma unroll
        for (int g = tid; g < 512; g += 256) {            // B: 32 rows x 16x16B
            int r = g >> 4, ch = g & 15;
            cp16(bb + r * B_ROW_B + ch * 16,
                 Bs + (size_t)(koff + r) * N3 + n0 + ch * 8);
        }
    };

    load_chunk(0, 0); asm volatile("cp.async.commit_group;" ::: "memory");
    load_chunk(1, 1); asm volatile("cp.async.commit_group;" ::: "memory");
    load_chunk(2, 2); asm volatile("cp.async.commit_group;" ::: "memory");

    float acc[4][4][4] = {};

    // ldmatrix lane addressing (same row/col pattern for A and B-trans)
    const int lrow = lane & 15;
    const int lcol8 = (lane >> 4) * 8;

    for (int c = 0; c < NCHUNK; c++) {
        asm volatile("cp.async.wait_group 2;" ::: "memory");
        __syncthreads();

        if (c + 3 < NCHUNK) load_chunk(c + 3, (c + 3) & 3);
        asm volatile("cp.async.commit_group;" ::: "memory");  // empty ok at tail

        const int s = c & 3;
        const uint32_t ab = sb + s * AS_BYTES;
        const uint32_t bb = sb + NSTAGE * AS_BYTES + s * BS_BYTES;

#pragma unroll
        for (int kk = 0; kk < 2; kk++) {                 // two k16 steps in BK=32
            uint32_t a[4][4];
#pragma unroll
            for (int mi = 0; mi < 4; mi++) {
                uint32_t addr = ab + (wm + mi * 16 + lrow) * A_ROW_B
                                   + (kk * 16 + lcol8) * 2;
                ldm_x4(a[mi][0], a[mi][1], a[mi][2], a[mi][3], addr);
            }
            uint32_t b[4][2];
#pragma unroll
            for (int np = 0; np < 2; np++) {             // two n16 groups
                uint32_t addr = bb + (kk * 16 + lrow) * B_ROW_B
                                   + (wn + np * 16 + lcol8) * 2;
                uint32_t r0, r1, r2, r3;
                ldm_x4t(r0, r1, r2, r3, addr);
                b[np * 2 + 0][0] = r0; b[np * 2 + 0][1] = r1;
                b[np * 2 + 1][0] = r2; b[np * 2 + 1][1] = r3;
            }
#pragma unroll
            for (int mi = 0; mi < 4; mi++)
#pragma unroll
                for (int ni = 0; ni < 4; ni++)
                    mma_bf16(acc[mi][ni], a[mi][0], a[mi][1], a[mi][2], a[mi][3],
                             b[ni][0], b[ni][1]);
        }
    }

    // epilogue: c-frag m16n8 -> direct fp32 stores (float2 per half-frag)
    const int g = lane >> 2, tig = lane & 3;
#pragma unroll
    for (int mi = 0; mi < 4; mi++) {
        int r0 = m0 + wm + mi * 16 + g;
#pragma unroll
        for (int ni = 0; ni < 4; ni++) {
            int cb = n0 + wn + ni * 8 + tig * 2;
            *reinterpret_cast<float2*>(C + (size_t)r0 * N3 + cb) =
                make_float2(acc[mi][ni][0], acc[mi][ni][1]);
            *reinterpret_cast<float2*>(C + (size_t)(r0 + 8) * N3 + cb) =
                make_float2(acc[mi][ni][2], acc[mi][ni][3]);
        }
    }
}

// ---------------------------------------------------------------------------
// Layer-0 GEMV + scans (unchanged from passing round-2 kernel)
// ---------------------------------------------------------------------------
__global__ void gemv_part_kernel(const float* __restrict__ inp,
                                 const float* __restrict__ W0,
                                 float* __restrict__ U0p) {
    int n = blockIdx.x * 128 + threadIdx.x;
    int k0 = blockIdx.y * 128;
    const float* wp = W0 + (size_t)k0 * N3 + n;
    float s = 0.f;
#pragma unroll 8
    for (int k = 0; k < 128; k++) { s = fmaf(inp[k0 + k], *wp, s); wp += N3; }
    U0p[blockIdx.y * N3 + n] = s;
}

__global__ void gemv_red_kernel(const float* __restrict__ U0p,
                                float* __restrict__ U0) {
    int n = blockIdx.x * 256 + threadIdx.x;
    if (n < N3) {
        float s = 0.f;
#pragma unroll
        for (int i = 0; i < 8; i++) s += U0p[i * N3 + n];
        U0[n] = s;
    }
}

__global__ void scan0_kernel(const float* __restrict__ U0,
                             const float* __restrict__ inp,
                             const float* __restrict__ c0,
                             const float* __restrict__ Vl,
                             const float* __restrict__ bl,
                             float* __restrict__ hout) {
    int j = blockIdx.x * blockDim.x + threadIdx.x;
    int h = j & (H_SZ - 1);
    float u0 = U0[h], u1 = U0[H_SZ + h], u2 = U0[2 * H_SZ + h];
    float xv = inp[h];
    float c = c0[j];
    float vf = Vl[h], vr = Vl[H_SZ + h];
    float bf = bl[h], br = bl[H_SZ + h];
    float* out = hout + j;
#pragma unroll 4
    for (int t = 0; t < T_LEN; t++) {
        float f = sigmoidf_(fmaf(vf, c, u1) + bf);
        c = fmaf(f, c - u0, u0);
        float r = sigmoidf_(fmaf(vr, c, u2) + br);
        *out = fmaf(r, c - xv, xv);
        out += B_SZ * H_SZ;
    }
}

__global__ void scan_kernel(const float* __restrict__ U,
                            const float* __restrict__ xin,
                            const float* __restrict__ c0,
                            const float* __restrict__ Vl,
                            const float* __restrict__ bl,
                            float* __restrict__ hout,
                            int final_out) {
    int j = blockIdx.x * blockDim.x + threadIdx.x;
    int b = j >> 10;
    int h = j & (H_SZ - 1);
    float c = c0[j];
    float vf = Vl[h], vr = Vl[H_SZ + h];
    float bf = bl[h], br = bl[H_SZ + h];

    const float* pu = U + (size_t)b * N3 + h;
    const float* px = xin + j;
    const size_t su = (size_t)B_SZ * N3;
    const size_t sx = (size_t)B_SZ * H_SZ;

    float u0 = pu[0], u1 = pu[H_SZ], u2 = pu[2 * H_SZ], xv = px[0];

    float* out;
    size_t ostride;
    if (final_out) { out = hout + (size_t)b * T_LEN * H_SZ + h; ostride = H_SZ; }
    else           { out = hout + j;                            ostride = (size_t)B_SZ * H_SZ; }

    for (int t = 0; t < T_LEN; t++) {
        pu += su; px += sx;
        float nu0 = pu[0], nu1 = pu[H_SZ], nu2 = pu[2 * H_SZ], nxv = px[0];
        float f = sigmoidf_(fmaf(vf, c, u1) + bf);
        c = fmaf(f, c - u0, u0);
        float r = sigmoidf_(fmaf(vr, c, u2) + br);
        *out = fmaf(r, c - xv, xv);
        out += ostride;
        u0 = nu0; u1 = nu1; u2 = nu2; xv = nxv;
    }
}

// ---------------------------------------------------------------------------
// Inputs: 0:c_n[B,H] 1:max_len 2:inp_vec[H] 3:W[NL,H,3H] 4:V[NL,2H] 5:bias[NL,2H]
// ---------------------------------------------------------------------------
extern "C" void kernel_launch(void* const* d_in, const int* in_sizes, int n_in,
                              void* d_out, int out_size) {
    const float* c_n  = (const float*)d_in[0];
    const float* inp  = (const float*)d_in[2];
    const float* W    = (const float*)d_in[3];
    const float* V    = (const float*)d_in[4];
    const float* bias = (const float*)d_in[5];
    float* out = (float*)d_out;

    float *pU0p, *pU0, *phA, *phB, *pU;
    __nv_bfloat16 *pAhi, *pAlo, *pWhi, *pWlo;
    cudaGetSymbolAddress((void**)&pU0p, g_U0p);
    cudaGetSymbolAddress((void**)&pU0,  g_U0);
    cudaGetSymbolAddress((void**)&phA,  g_hA);
    cudaGetSymbolAddress((void**)&phB,  g_hB);
    cudaGetSymbolAddress((void**)&pU,   g_U);
    cudaGetSymbolAddress((void**)&pAhi, g_Ahi);
    cudaGetSymbolAddress((void**)&pAlo, g_Alo);
    cudaGetSymbolAddress((void**)&pWhi, g_Whi);
    cudaGetSymbolAddress((void**)&pWlo, g_Wlo);

    cudaFuncSetAttribute(mma_gemm_kernel,
                         cudaFuncAttributeMaxDynamicSharedMemorySize, SMEM_TOTAL);

    // W split for layers 1..3 (elementwise, layout preserved)
    split_w_kernel<<<(int)(((size_t)3 * KDIM * N3) / 1024), 256>>>(W, pWhi, pWlo);

    // Layer 0: GEMV + register-resident scan
    gemv_part_kernel<<<dim3(24, 8), 128>>>(inp, W, pU0p);
    gemv_red_kernel<<<12, 256>>>(pU0p, pU0);
    scan0_kernel<<<64, 256>>>(pU0, inp, c_n, V, bias, phA);

    // Layers 1..3: split A -> mma GEMM -> scan
    const float* cur = phA;
    for (int l = 1; l < 4; l++) {
        split_a_kernel<<<(int)(((size_t)M_ROWS * KDIM) / 1024), 256>>>(cur, pAhi, pAlo);
        mma_gemm_kernel<<<dim3(N3 / BN, M_ROWS / BM), 256, SMEM_TOTAL>>>(
            pAhi, pAlo, pWhi, pWlo, pU, l - 1);
        int fin = (l == 3);
        float* nxt = fin ? out : ((cur == phA) ? phB : phA);
        scan_kernel<<<64, 256>>>(pU, cur, c_n,
                                 V + (size_t)l * 2 * H_SZ,
                                 bias + (size_t)l * 2 * H_SZ,
                                 nxt, fin);
        cur = nxt;
    }
}

// round 6
// speedup vs baseline: 1.8373x; 1.2795x over previous
#include <cuda_runtime.h>
#include <cuda_bf16.h>
#include <cstdint>
#include <cstddef>

#define T_LEN 2048
#define B_SZ  16
#define H_SZ  1024
#define N3    (3 * H_SZ)
#define M_ROWS (T_LEN * B_SZ)
#define KDIM  H_SZ
#define LOG2E 1.4426950408889634f

// mma.sync GEMM tiling
#define BM 128
#define BN 128
#define BK 32
#define NSTAGE 4
#define NCHUNK 96                    // 3 split passes * (1024/32)
#define A_ROW_B 80                   // 32 bf16 = 64B data, padded to 80B (5x16B)
#define B_ROW_B 272                  // 128 bf16 = 256B data, padded to 272B (17x16B)
#define AS_BYTES (BM * A_ROW_B)      // 10240
#define BS_BYTES (BK * B_ROW_B)      // 8704
#define SMEM_TOTAL (NSTAGE * (AS_BYTES + BS_BYTES))   // 75776

// ---------------- scratch (device globals; allocation-free rule) -----------
__device__ float g_U0p[8 * N3];
__device__ float g_U0[N3];
__device__ float g_hA[(size_t)M_ROWS * H_SZ + (size_t)B_SZ * H_SZ];
__device__ float g_hB[(size_t)M_ROWS * H_SZ + (size_t)B_SZ * H_SZ];
__device__ float g_U [(size_t)M_ROWS * N3  + (size_t)B_SZ * N3];
__device__ __nv_bfloat16 g_Ahi[(size_t)M_ROWS * KDIM];
__device__ __nv_bfloat16 g_Alo[(size_t)M_ROWS * KDIM];
__device__ __nv_bfloat16 g_Whi[(size_t)3 * KDIM * N3];
__device__ __nv_bfloat16 g_Wlo[(size_t)3 * KDIM * N3];

__device__ __forceinline__ float fast_ex2(float x) {
    float y; asm("ex2.approx.f32 %0, %1;" : "=f"(y) : "f"(x)); return y;
}
__device__ __forceinline__ float fast_rcp(float x) {
    float y; asm("rcp.approx.f32 %0, %1;" : "=f"(y) : "f"(x)); return y;
}

__device__ __forceinline__ uint32_t smem_u32(const void* p) {
    uint32_t a;
    asm("{ .reg .u64 t; cvta.to.shared.u64 t, %1; cvt.u32.u64 %0, t; }"
        : "=r"(a) : "l"(p));
    return a;
}
__device__ __forceinline__ void cp16(uint32_t dst, const void* src) {
    asm volatile("cp.async.cg.shared.global [%0], [%1], 16;"
                 :: "r"(dst), "l"(src) : "memory");
}
__device__ __forceinline__ void ldm_x4(uint32_t& r0, uint32_t& r1,
                                       uint32_t& r2, uint32_t& r3, uint32_t a) {
    asm volatile("ldmatrix.sync.aligned.m8n8.x4.shared.b16 {%0,%1,%2,%3}, [%4];"
                 : "=r"(r0), "=r"(r1), "=r"(r2), "=r"(r3) : "r"(a));
}
__device__ __forceinline__ void ldm_x4t(uint32_t& r0, uint32_t& r1,
                                        uint32_t& r2, uint32_t& r3, uint32_t a) {
    asm volatile("ldmatrix.sync.aligned.m8n8.x4.trans.shared.b16 {%0,%1,%2,%3}, [%4];"
                 : "=r"(r0), "=r"(r1), "=r"(r2), "=r"(r3) : "r"(a));
}
__device__ __forceinline__ void mma_bf16(float* c, uint32_t a0, uint32_t a1,
                                         uint32_t a2, uint32_t a3,
                                         uint32_t b0, uint32_t b1) {
    asm volatile(
        "mma.sync.aligned.m16n8k16.row.col.f32.bf16.bf16.f32 "
        "{%0,%1,%2,%3}, {%4,%5,%6,%7}, {%8,%9}, {%0,%1,%2,%3};"
        : "+f"(c[0]), "+f"(c[1]), "+f"(c[2]), "+f"(c[3])
        : "r"(a0), "r"(a1), "r"(a2), "r"(a3), "r"(b0), "r"(b1));
}

// ---------------------------------------------------------------------------
// W split (elementwise, layers 1..3, [K,N] layout preserved)
// ---------------------------------------------------------------------------
__global__ void split_w_kernel(const float* __restrict__ W,
                               __nv_bfloat16* __restrict__ hi,
                               __nv_bfloat16* __restrict__ lo) {
    size_t i = ((size_t)blockIdx.x * 256 + threadIdx.x) * 4;
    const float* src = W + (size_t)KDIM * N3;    // skip layer 0
    float4 v = *reinterpret_cast<const float4*>(src + i);
    __nv_bfloat16 h0 = __float2bfloat16(v.x), h1 = __float2bfloat16(v.y);
    __nv_bfloat16 h2 = __float2bfloat16(v.z), h3 = __float2bfloat16(v.w);
    __nv_bfloat162 hp0(h0, h1), hp1(h2, h3);
    __nv_bfloat162 lp0(__float2bfloat16(v.x - __bfloat162float(h0)),
                       __float2bfloat16(v.y - __bfloat162float(h1)));
    __nv_bfloat162 lp1(__float2bfloat16(v.z - __bfloat162float(h2)),
                       __float2bfloat16(v.w - __bfloat162float(h3)));
    *reinterpret_cast<__nv_bfloat162*>(hi + i)     = hp0;
    *reinterpret_cast<__nv_bfloat162*>(hi + i + 2) = hp1;
    *reinterpret_cast<__nv_bfloat162*>(lo + i)     = lp0;
    *reinterpret_cast<__nv_bfloat162*>(lo + i + 2) = lp1;
}

// ---------------------------------------------------------------------------
// bf16 mma.sync GEMM with 3-pass split accumulation. 2 CTAs/SM.
// ---------------------------------------------------------------------------
__global__ void __launch_bounds__(256, 2)
mma_gemm_kernel(const __nv_bfloat16* __restrict__ Ahi,
                const __nv_bfloat16* __restrict__ Alo,
                const __nv_bfloat16* __restrict__ Whi,
                const __nv_bfloat16* __restrict__ Wlo,
                float* __restrict__ C, int layer) {
    extern __shared__ char smem[];
    const uint32_t sb = smem_u32(smem);
    const int tid = threadIdx.x;
    const int wid = tid >> 5, lane = tid & 31;
    const int m0 = blockIdx.y * BM;
    const int n0 = blockIdx.x * BN;
    const int wm = (wid & 1) * 64;
    const int wn = (wid >> 1) * 32;

    const __nv_bfloat16* Bhi = Whi + (size_t)layer * KDIM * N3;
    const __nv_bfloat16* Blo = Wlo + (size_t)layer * KDIM * N3;

    auto load_chunk = [&](int c, int s) {
        int p = c >> 5;
        int koff = (c & 31) * BK;
        const __nv_bfloat16* As = (p == 2) ? Alo : Ahi;
        const __nv_bfloat16* Bs = (p == 1) ? Blo : Bhi;
        uint32_t ab = sb + s * AS_BYTES;
        uint32_t bb = sb + NSTAGE * AS_BYTES + s * BS_BYTES;
#pragma unroll
        for (int g = tid; g < 512; g += 256) {            // A: 128 rows x 4x16B
            int r = g >> 2, ch = g & 3;
            cp16(ab + r * A_ROW_B + ch * 16,
                 As + (size_t)(m0 + r) * KDIM + koff + ch * 8);
        }
#pragma unroll
        for (int g = tid; g < 512; g += 256) {            // B: 32 rows x 16x16B
            int r = g >> 4, ch = g & 15;
            cp16(bb + r * B_ROW_B + ch * 16,
                 Bs + (size_t)(koff + r) * N3 + n0 + ch * 8);
        }
    };

    load_chunk(0, 0); asm volatile("cp.async.commit_group;" ::: "memory");
    load_chunk(1, 1); asm volatile("cp.async.commit_group;" ::: "memory");
    load_chunk(2, 2); asm volatile("cp.async.commit_group;" ::: "memory");

    float acc[4][4][4] = {};
    const int lrow = lane & 15;
    const int lcol8 = (lane >> 4) * 8;

    for (int c = 0; c < NCHUNK; c++) {
        asm volatile("cp.async.wait_group 2;" ::: "memory");
        __syncthreads();

        if (c + 3 < NCHUNK) load_chunk(c + 3, (c + 3) & 3);
        asm volatile("cp.async.commit_group;" ::: "memory");

        const int s = c & 3;
        const uint32_t ab = sb + s * AS_BYTES;
        const uint32_t bb = sb + NSTAGE * AS_BYTES + s * BS_BYTES;

#pragma unroll
        for (int kk = 0; kk < 2; kk++) {
            uint32_t a[4][4];
#pragma unroll
            for (int mi = 0; mi < 4; mi++) {
                uint32_t addr = ab + (wm + mi * 16 + lrow) * A_ROW_B
                                   + (kk * 16 + lcol8) * 2;
                ldm_x4(a[mi][0], a[mi][1], a[mi][2], a[mi][3], addr);
            }
            uint32_t b[4][2];
#pragma unroll
            for (int np = 0; np < 2; np++) {
                uint32_t addr = bb + (kk * 16 + lrow) * B_ROW_B
                                   + (wn + np * 16 + lcol8) * 2;
                uint32_t r0, r1, r2, r3;
                ldm_x4t(r0, r1, r2, r3, addr);
                b[np * 2 + 0][0] = r0; b[np * 2 + 0][1] = r1;
                b[np * 2 + 1][0] = r2; b[np * 2 + 1][1] = r3;
            }
#pragma unroll
            for (int mi = 0; mi < 4; mi++)
#pragma unroll
                for (int ni = 0; ni < 4; ni++)
                    mma_bf16(acc[mi][ni], a[mi][0], a[mi][1], a[mi][2], a[mi][3],
                             b[ni][0], b[ni][1]);
        }
    }

    const int g = lane >> 2, tig = lane & 3;
#pragma unroll
    for (int mi = 0; mi < 4; mi++) {
        int r0 = m0 + wm + mi * 16 + g;
#pragma unroll
        for (int ni = 0; ni < 4; ni++) {
            int cb = n0 + wn + ni * 8 + tig * 2;
            *reinterpret_cast<float2*>(C + (size_t)r0 * N3 + cb) =
                make_float2(acc[mi][ni][0], acc[mi][ni][1]);
            *reinterpret_cast<float2*>(C + (size_t)(r0 + 8) * N3 + cb) =
                make_float2(acc[mi][ni][2], acc[mi][ni][3]);
        }
    }
}

// ---------------------------------------------------------------------------
// Layer-0 GEMV
// ---------------------------------------------------------------------------
__global__ void gemv_part_kernel(const float* __restrict__ inp,
                                 const float* __restrict__ W0,
                                 float* __restrict__ U0p) {
    int n = blockIdx.x * 128 + threadIdx.x;
    int k0 = blockIdx.y * 128;
    const float* wp = W0 + (size_t)k0 * N3 + n;
    float s = 0.f;
#pragma unroll 8
    for (int k = 0; k < 128; k++) { s = fmaf(inp[k0 + k], *wp, s); wp += N3; }
    U0p[blockIdx.y * N3 + n] = s;
}

__global__ void gemv_red_kernel(const float* __restrict__ U0p,
                                float* __restrict__ U0) {
    int n = blockIdx.x * 256 + threadIdx.x;
    if (n < N3) {
        float s = 0.f;
#pragma unroll
        for (int i = 0; i < 8; i++) s += U0p[i * N3 + n];
        U0[n] = s;
    }
}

// ---------------------------------------------------------------------------
// Layer-0 scan: fused split-bf16 output (feeds layer-1 GEMM directly)
// ---------------------------------------------------------------------------
__global__ void scan0_kernel(const float* __restrict__ U0,
                             const float* __restrict__ inp,
                             const float* __restrict__ c0,
                             const float* __restrict__ Vl,
                             const float* __restrict__ bl,
                             float* __restrict__ hout,
                             __nv_bfloat16* __restrict__ ahi,
                             __nv_bfloat16* __restrict__ alo) {
    int j = blockIdx.x * blockDim.x + threadIdx.x;
    int h = j & (H_SZ - 1);
    float u0 = U0[h], u1 = U0[H_SZ + h], u2 = U0[2 * H_SZ + h];
    float xv = inp[h];
    float c = c0[j];
    float vf = Vl[h], vr = Vl[H_SZ + h];
    float bf = bl[h], br = bl[H_SZ + h];
    // f = 1/(1+ex2(nvf*c + nf0));  (minus-log2e factors folded in)
    float nvf = -LOG2E * vf,         nf0 = -LOG2E * (u1 + bf);
    float nvr = -LOG2E * vr,         nr0 = -LOG2E * (u2 + br);
    size_t o = j;
#pragma unroll 4
    for (int t = 0; t < T_LEN; t++) {
        float f = fast_rcp(1.0f + fast_ex2(fmaf(nvf, c, nf0)));
        c = fmaf(f, c - u0, u0);
        float r = fast_rcp(1.0f + fast_ex2(fmaf(nvr, c, nr0)));
        float hv = fmaf(r, c - xv, xv);
        hout[o] = hv;
        __nv_bfloat16 hh = __float2bfloat16(hv);
        ahi[o] = hh;
        alo[o] = __float2bfloat16(hv - __bfloat162float(hh));
        o += (size_t)B_SZ * H_SZ;
    }
}

// ---------------------------------------------------------------------------
// Generic scan (layers 1..3), fused split output for the next GEMM.
// final_out: write permuted [B,T,H] into d_out, no splits.
// ---------------------------------------------------------------------------
__global__ void scan_kernel(const float* __restrict__ U,
                            const float* __restrict__ xin,
                            const float* __restrict__ c0,
                            const float* __restrict__ Vl,
                            const float* __restrict__ bl,
                            float* __restrict__ hout,
                            __nv_bfloat16* __restrict__ ahi,
                            __nv_bfloat16* __restrict__ alo,
                            int final_out) {
    int j = blockIdx.x * blockDim.x + threadIdx.x;
    int b = j >> 10;
    int h = j & (H_SZ - 1);
    float c = c0[j];
    float vf = Vl[h], vr = Vl[H_SZ + h];
    float bf = bl[h], br = bl[H_SZ + h];
    float nvf = -LOG2E * vf, nvr = -LOG2E * vr;
    float nbf = -LOG2E * bf, nbr = -LOG2E * br;

    const float* pu = U + (size_t)b * N3 + h;
    const float* px = xin + j;
    const size_t su = (size_t)B_SZ * N3;
    const size_t sx = (size_t)B_SZ * H_SZ;

    float u0 = pu[0], xv = px[0];
    float pf = fmaf(-LOG2E, pu[H_SZ], nbf);        // -log2e*(u1+bf)
    float pr = fmaf(-LOG2E, pu[2 * H_SZ], nbr);

    float* outp;
    size_t ostride;
    if (final_out) { outp = hout + (size_t)b * T_LEN * H_SZ + h; ostride = H_SZ; }
    else           { outp = hout + j;                            ostride = sx; }
    size_t oa = j;

    for (int t = 0; t < T_LEN; t++) {
        pu += su; px += sx;                          // prefetch t+1 (padded)
        float nu0 = pu[0], nxv = px[0];
        float npf = fmaf(-LOG2E, pu[H_SZ], nbf);
        float npr = fmaf(-LOG2E, pu[2 * H_SZ], nbr);

        float f = fast_rcp(1.0f + fast_ex2(fmaf(nvf, c, pf)));
        c = fmaf(f, c - u0, u0);
        float r = fast_rcp(1.0f + fast_ex2(fmaf(nvr, c, pr)));
        float hv = fmaf(r, c - xv, xv);
        *outp = hv;
        outp += ostride;
        if (!final_out) {
            __nv_bfloat16 hh = __float2bfloat16(hv);
            ahi[oa] = hh;
            alo[oa] = __float2bfloat16(hv - __bfloat162float(hh));
            oa += sx;
        }
        u0 = nu0; xv = nxv; pf = npf; pr = npr;
    }
}

// ---------------------------------------------------------------------------
// Inputs: 0:c_n[B,H] 1:max_len 2:inp_vec[H] 3:W[NL,H,3H] 4:V[NL,2H] 5:bias[NL,2H]
// ---------------------------------------------------------------------------
extern "C" void kernel_launch(void* const* d_in, const int* in_sizes, int n_in,
                              void* d_out, int out_size) {
    const float* c_n  = (const float*)d_in[0];
    const float* inp  = (const float*)d_in[2];
    const float* W    = (const float*)d_in[3];
    const float* V    = (const float*)d_in[4];
    const float* bias = (const float*)d_in[5];
    float* out = (float*)d_out;

    float *pU0p, *pU0, *phA, *phB, *pU;
    __nv_bfloat16 *pAhi, *pAlo, *pWhi, *pWlo;
    cudaGetSymbolAddress((void**)&pU0p, g_U0p);
    cudaGetSymbolAddress((void**)&pU0,  g_U0);
    cudaGetSymbolAddress((void**)&phA,  g_hA);
    cudaGetSymbolAddress((void**)&phB,  g_hB);
    cudaGetSymbolAddress((void**)&pU,   g_U);
    cudaGetSymbolAddress((void**)&pAhi, g_Ahi);
    cudaGetSymbolAddress((void**)&pAlo, g_Alo);
    cudaGetSymbolAddress((void**)&pWhi, g_Whi);
    cudaGetSymbolAddress((void**)&pWlo, g_Wlo);

    cudaFuncSetAttribute(mma_gemm_kernel,
                         cudaFuncAttributeMaxDynamicSharedMemorySize, SMEM_TOTAL);

    split_w_kernel<<<(int)(((size_t)3 * KDIM * N3) / 1024), 256>>>(W, pWhi, pWlo);

    // Layer 0: GEMV + scan (fused split output)
    gemv_part_kernel<<<dim3(24, 8), 128>>>(inp, W, pU0p);
    gemv_red_kernel<<<12, 256>>>(pU0p, pU0);
    scan0_kernel<<<128, 128>>>(pU0, inp, c_n, V, bias, phA, pAhi, pAlo);

    // Layers 1..3: GEMM -> scan (scan emits next layer's A splits)
    const float* cur = phA;
    for (int l = 1; l < 4; l++) {
        mma_gemm_kernel<<<dim3(N3 / BN, M_ROWS / BM), 256, SMEM_TOTAL>>>(
            pAhi, pAlo, pWhi, pWlo, pU, l - 1);
        int fin = (l == 3);
        float* nxt = fin ? out : ((cur == phA) ? phB : phA);
        scan_kernel<<<128, 128>>>(pU, cur, c_n,
                                  V + (size_t)l * 2 * H_SZ,
                                  bias + (size_t)l * 2 * H_SZ,
                                  nxt, pAhi, pAlo, fin);
        cur = nxt;
    }
}